// round 10
// baseline (speedup 1.0000x reference)
#include <cuda_runtime.h>
#include <cuda_bf16.h>
#include <math.h>
#include <stdint.h>

#define NN 16000
#define EE 256000
#define DIN 256
#define HH 8
#define HD 256

#define EOUT_OFF  (NN * HD)             // 4,096,000
#define COORD_OFF (NN * HD + EE * HD)   // 69,632,000

// ---- scratch (static device globals; no runtime allocation) ----
__device__ float g_q[NN * HD];
__device__ float g_k[NN * HD];
__device__ float g_v[NN * HD];
__device__ float g_ax[EE * HH];
__device__ int   g_row[EE];
__device__ int   g_col[EE];
__device__ int   g_deg[NN];
__device__ int   g_off[NN + 1];
__device__ int   g_cursor[NN];
__device__ int   g_eid[EE];
__device__ int   g_bsum[64];
__device__ int   g_bsumx[64];
// transposed (K-major, [n*256+k]) bf16 hi/lo weights: mats 0..3 = Wq,Wk,Wv,We
__device__ __nv_bfloat16 g_bt_hi[4 * 65536];
__device__ __nv_bfloat16 g_bt_lo[4 * 65536];

// ===========================================================================
// MMA / async-copy helpers (sm_80-baseline — compiles for plain sm_103)
// ===========================================================================
__device__ __forceinline__ uint32_t smem_u32(const void* p) {
    return (uint32_t)__cvta_generic_to_shared(p);
}

#define LDSM4(r, addr)                                                        \
    asm volatile("ldmatrix.sync.aligned.m8n8.x4.shared.b16 {%0,%1,%2,%3}, [%4];" \
        : "=r"((r)[0]), "=r"((r)[1]), "=r"((r)[2]), "=r"((r)[3]) : "r"(addr))

#define MMA16816(c, a, b0, b1)                                                \
    asm volatile("mma.sync.aligned.m16n8k16.row.col.f32.bf16.bf16.f32 "       \
        "{%0,%1,%2,%3}, {%4,%5,%6,%7}, {%8,%9}, {%0,%1,%2,%3};"               \
        : "+f"((c)[0]), "+f"((c)[1]), "+f"((c)[2]), "+f"((c)[3])              \
        : "r"((a)[0]), "r"((a)[1]), "r"((a)[2]), "r"((a)[3]),                 \
          "r"(b0), "r"(b1))

#define CP_ASYNC16(dst, src)                                                  \
    asm volatile("cp.async.cg.shared.global [%0], [%1], 16;"                  \
        :: "r"(dst), "l"(src))
#define CP_COMMIT() asm volatile("cp.async.commit_group;")
#define CP_WAIT0()  asm volatile("cp.async.wait_group 0;")

// SMEM layout (byte offsets into extern shared)
// A tile: 64 rows x 64 k bf16, stride 80 elems (160B) -> 10240 B each (hi/lo)
// B tile: 128 rows x 64 k bf16, stride 80 -> 20480 B each; double-buffered
#define OFF_AHI   0u
#define OFF_ALO   10240u
#define OFF_B0HI  20480u
#define OFF_B0LO  40960u
#define OFF_B1HI  61440u
#define OFF_B1LO  81920u
#define OFF_DIST  102400u
#define OFF_RN    102656u
#define OFF_CN    102912u
#define SMEM_TOT  103168u

// ===========================================================================
// Pipelined GEMM mainloop. Per thread acc[2][4][4] = fragment of
// D[64,128] = A[64,256] @ B[128,256]^T (bf16 hi/lo 3-pass).
// A prefetched 1 chunk ahead in registers (fp32->bf16 split at STS time);
// B staged via cp.async into double buffer.
// 8 warps: wm = wid&1 (32 rows), wn = wid>>1 (32 cols).
// ===========================================================================
__device__ __forceinline__ void gemm_tile(
    char* sm, uint32_t sb,
    const float* __restrict__ Asrc,
    const __nv_bfloat16* __restrict__ bhi_g,
    const __nv_bfloat16* __restrict__ blo_g,
    int half, int tid, float acc[2][4][4])
{
    const int wid = tid >> 5, lane = tid & 31;
    const int wm = wid & 1, wn = wid >> 1;
    const uint32_t lrow = lane & 15;
    const uint32_t lkh  = ((lane >> 4) & 1) << 3;

    const int ar = tid >> 4, aqd = tid & 15;        // A: rows ar, ar+16, ar+32, ar+48
    const int bn = tid >> 3, bgq = tid & 7;         // B: rows bn, bn+32, bn+64, bn+96

    // ---- prologue: B chunk0 via cp.async, A chunk0 into regs -------------
    float4 aR[4];
    #pragma unroll
    for (int s = 0; s < 4; s++)
        aR[s] = *(const float4*)(Asrc + (size_t)(ar + s*16) * 256 + aqd * 4);
    #pragma unroll
    for (int s = 0; s < 4; s++) {
        int n = bn + s*32;
        size_t src = (size_t)(half*128 + n) * 256 + bgq * 8;
        uint32_t d = (uint32_t)(n * 160 + bgq * 16);
        CP_ASYNC16(sb + OFF_B0HI + d, bhi_g + src);
        CP_ASYNC16(sb + OFF_B0LO + d, blo_g + src);
    }
    CP_COMMIT();

    for (int chunk = 0; chunk < 4; chunk++) {
        const uint32_t bufB = (chunk & 1) ? OFF_B1HI : OFF_B0HI;

        CP_WAIT0();              // B_chunk arrived (only group outstanding)
        __syncthreads();         // previous compute done (A smem / B buf free)

        // ---- STS A_chunk from regs (fp32 -> bf16 hi/lo split) -----------
        #pragma unroll
        for (int s = 0; s < 4; s++) {
            float4 a = aR[s];
            __nv_bfloat16 h0 = __float2bfloat16(a.x);
            __nv_bfloat16 h1 = __float2bfloat16(a.y);
            __nv_bfloat16 h2 = __float2bfloat16(a.z);
            __nv_bfloat16 h3 = __float2bfloat16(a.w);
            __nv_bfloat16 l0 = __float2bfloat16(a.x - __bfloat162float(h0));
            __nv_bfloat16 l1 = __float2bfloat16(a.y - __bfloat162float(h1));
            __nv_bfloat16 l2 = __float2bfloat16(a.z - __bfloat162float(h2));
            __nv_bfloat16 l3 = __float2bfloat16(a.w - __bfloat162float(h3));
            uint2 hv, lv;
            hv.x = ((uint32_t)__bfloat16_as_ushort(h1) << 16) | __bfloat16_as_ushort(h0);
            hv.y = ((uint32_t)__bfloat16_as_ushort(h3) << 16) | __bfloat16_as_ushort(h2);
            lv.x = ((uint32_t)__bfloat16_as_ushort(l1) << 16) | __bfloat16_as_ushort(l0);
            lv.y = ((uint32_t)__bfloat16_as_ushort(l3) << 16) | __bfloat16_as_ushort(l2);
            uint32_t d = (uint32_t)((ar + s*16) * 160 + aqd * 8);
            *(uint2*)(sm + OFF_AHI + d) = hv;
            *(uint2*)(sm + OFF_ALO + d) = lv;
        }

        // ---- prefetch chunk+1 (overlaps with compute below) -------------
        if (chunk < 3) {
            const int k0n = (chunk + 1) * 64;
            #pragma unroll
            for (int s = 0; s < 4; s++)
                aR[s] = *(const float4*)(Asrc + (size_t)(ar + s*16) * 256 + k0n + aqd * 4);
            const uint32_t nb = ((chunk + 1) & 1) ? OFF_B1HI : OFF_B0HI;
            #pragma unroll
            for (int s = 0; s < 4; s++) {
                int n = bn + s*32;
                size_t src = (size_t)(half*128 + n) * 256 + k0n + bgq * 8;
                uint32_t d = (uint32_t)(n * 160 + bgq * 16);
                CP_ASYNC16(sb + nb + d, bhi_g + src);
                CP_ASYNC16(sb + nb + 20480u + d, blo_g + src);
            }
            CP_COMMIT();
        }

        __syncthreads();

        // ---- compute 4 k16 steps ----------------------------------------
        #pragma unroll
        for (int ks = 0; ks < 4; ks++) {
            const uint32_t koff = (uint32_t)(ks * 16 + lkh) * 2;
            uint32_t ah[2][4], al[2][4], bh[2][4], bl[2][4];
            #pragma unroll
            for (int mi = 0; mi < 2; mi++) {
                uint32_t addr = sb + OFF_AHI + (uint32_t)(wm*32 + mi*16 + lrow) * 160 + koff;
                LDSM4(ah[mi], addr);
                LDSM4(al[mi], addr + (OFF_ALO - OFF_AHI));
            }
            #pragma unroll
            for (int gj = 0; gj < 2; gj++) {
                uint32_t addr = sb + bufB + (uint32_t)(wn*32 + gj*16 + lrow) * 160 + koff;
                LDSM4(bh[gj], addr);
                LDSM4(bl[gj], addr + 20480u);
            }
            #pragma unroll
            for (int mi = 0; mi < 2; mi++)
                #pragma unroll
                for (int ni = 0; ni < 4; ni++) {
                    int gj = ni >> 1, up = ni & 1;
                    uint32_t b0h = bh[gj][up], b1h = bh[gj][up + 2];
                    uint32_t b0l = bl[gj][up], b1l = bl[gj][up + 2];
                    MMA16816(acc[mi][ni], ah[mi], b0h, b1h);
                    MMA16816(acc[mi][ni], ah[mi], b0l, b1l);
                    MMA16816(acc[mi][ni], al[mi], b0h, b1h);
                }
        }
    }
}

// ===========================================================================
// Preprocessing kernels
// ===========================================================================
__global__ void zero_deg_kernel() {
    int i = blockIdx.x * blockDim.x + threadIdx.x;
    if (i < NN) g_deg[i] = 0;
}

// Converts indices (self-detecting int64 vs int32) + destination histogram.
__global__ void convert_hist_kernel(const void* ei) {
    __shared__ int s_is64;
    if (threadIdx.x < 32) {
        const long long* p = (const long long*)ei;
        int bad = 0;
        for (int i = threadIdx.x; i < 512; i += 32) {
            long long v = p[i];
            if (v < 0 || v >= NN) bad = 1;
        }
        bad = __any_sync(0xffffffffu, bad);
        if (threadIdx.x == 0) s_is64 = bad ? 0 : 1;
    }
    __syncthreads();
    int i = blockIdx.x * blockDim.x + threadIdx.x;
    if (i < EE) {
        int r, c;
        if (s_is64) {
            const long long* p = (const long long*)ei;
            r = (int)p[i]; c = (int)p[EE + i];
        } else {
            const int* p = (const int*)ei;
            r = p[i]; c = p[EE + i];
        }
        g_row[i] = r; g_col[i] = c;
        atomicAdd(&g_deg[c], 1);
    }
}

// 3-phase multi-block exclusive scan of g_deg (16000 -> g_off, g_cursor).
#define SCAN_BLOCKS 63
__global__ void scanA_kernel() {
    __shared__ int s[256];
    int b = blockIdx.x, t = threadIdx.x;
    int i = b * 256 + t;
    int v = (i < NN) ? g_deg[i] : 0;
    s[t] = v;
    __syncthreads();
    #pragma unroll
    for (int off = 1; off < 256; off <<= 1) {
        int u = (t >= off) ? s[t - off] : 0;
        __syncthreads();
        s[t] += u;
        __syncthreads();
    }
    if (i < NN) g_off[i] = s[t] - v;   // block-local exclusive
    if (t == 255) g_bsum[b] = s[255];
}

__global__ void scanB_kernel() {
    __shared__ int s[SCAN_BLOCKS];
    int t = threadIdx.x;
    if (t < SCAN_BLOCKS) s[t] = g_bsum[t];
    __syncthreads();
    if (t == 0) {
        int run = 0;
        for (int b = 0; b < SCAN_BLOCKS; b++) {
            int v = s[b];
            s[b] = run;
            run += v;
        }
        g_off[NN] = run;
    }
    __syncthreads();
    if (t < SCAN_BLOCKS) g_bsumx[t] = s[t];
}

__global__ void scanC_kernel() {
    int b = blockIdx.x, t = threadIdx.x;
    int i = b * 256 + t;
    if (i < NN) {
        int o = g_off[i] + g_bsumx[b];
        g_off[i] = o;
        g_cursor[i] = o;
    }
}

__global__ void fill_kernel() {
    int i = blockIdx.x * blockDim.x + threadIdx.x;
    if (i < EE) {
        int c = g_col[i];
        int p = atomicAdd(&g_cursor[c], 1);
        g_eid[p] = i;
    }
}

// Transpose weights to K-major bf16 hi/lo. grid (256, 4)
__global__ void wtrans_kernel(const float* __restrict__ Wq, const float* __restrict__ Wk,
                              const float* __restrict__ Wv, const float* __restrict__ We) {
    int mat = blockIdx.y;
    const float* W = (mat == 0) ? Wq : (mat == 1) ? Wk : (mat == 2) ? Wv : We;
    int idx = blockIdx.x * 256 + threadIdx.x;
    int n = idx & 255;
    int k = idx >> 8;
    float v = W[(size_t)k * 256 + n];
    __nv_bfloat16 h = __float2bfloat16(v);
    __nv_bfloat16 l = __float2bfloat16(v - __bfloat162float(h));
    g_bt_hi[(size_t)mat * 65536 + (size_t)n * 256 + k] = h;
    g_bt_lo[(size_t)mat * 65536 + (size_t)n * 256 + k] = l;
}

// ===========================================================================
// q/k/v tensor-core GEMM. grid (250, 2, 3), 256 threads.
// ===========================================================================
__global__ __launch_bounds__(256, 2) void qkv_mma_kernel(const float* __restrict__ x) {
    extern __shared__ char sm[];
    uint32_t sb = smem_u32(sm);
    int tid = threadIdx.x;
    int m0   = blockIdx.x * 64;
    int half = blockIdx.y;
    int mat  = blockIdx.z;

    float acc[2][4][4] = {};
    gemm_tile(sm, sb, x + (size_t)m0 * 256,
              g_bt_hi + (size_t)mat * 65536, g_bt_lo + (size_t)mat * 65536,
              half, tid, acc);

    float* outp = (mat == 0) ? g_q : (mat == 1) ? g_k : g_v;
    int wid = tid >> 5, lane = tid & 31;
    int wm = wid & 1, wn = wid >> 1;
    int g = lane >> 2, quad = lane & 3;
    int cbase = half * 128 + wn * 32 + quad * 2;

    #pragma unroll
    for (int mi = 0; mi < 2; mi++)
        #pragma unroll
        for (int hh = 0; hh < 2; hh++) {
            int row = m0 + wm*32 + mi*16 + hh*8 + g;
            #pragma unroll
            for (int ni = 0; ni < 4; ni++)
                *(float2*)(outp + (size_t)row * 256 + cbase + ni*8) =
                    make_float2(acc[mi][ni][hh*2], acc[mi][ni][hh*2+1]);
        }
}

// ===========================================================================
// Edge GEMM + fused attention epilogue. grid 8000 (tile = bid>>1,
// half = bid&1 so both halves of a tile are co-resident -> L2 reuse).
// Warp wn covers exactly one head (32 cols) -> head sum is a quad shuffle.
// ===========================================================================
__global__ __launch_bounds__(256, 2) void edge_mma_kernel(
    const float* __restrict__ edge_attr,
    const float* __restrict__ coords,
    const float* __restrict__ We,
    float* __restrict__ out)
{
    extern __shared__ char sm[];
    uint32_t sb = smem_u32(sm);
    int tid = threadIdx.x;
    int e0   = (blockIdx.x >> 1) * 64;
    int half = blockIdx.x & 1;

    if (tid < 64) {
        int e = e0 + tid;
        int r = g_row[e], c = g_col[e];
        ((int*)(sm + OFF_RN))[tid] = r;
        ((int*)(sm + OFF_CN))[tid] = c;
        float dx = coords[r*3+0] - coords[c*3+0];
        float dy = coords[r*3+1] - coords[c*3+1];
        float dz = coords[r*3+2] - coords[c*3+2];
        ((float*)(sm + OFF_DIST))[tid] = 0.1f * sqrtf(dx*dx + dy*dy + dz*dz);
    }

    float acc[2][4][4] = {};
    gemm_tile(sm, sb, edge_attr + (size_t)e0 * 256,
              g_bt_hi + (size_t)3 * 65536, g_bt_lo + (size_t)3 * 65536,
              half, tid, acc);

    int wid = tid >> 5, lane = tid & 31;
    int wm = wid & 1, wn = wid >> 1;
    int g = lane >> 2, quad = lane & 3;
    int head  = half * 4 + wn;
    int cbase = half * 128 + wn * 32 + quad * 2;

    float wl[4][2];
    #pragma unroll
    for (int ni = 0; ni < 4; ni++) {
        float2 w = *(const float2*)(We + (size_t)256 * 256 + cbase + ni*8);
        wl[ni][0] = w.x; wl[ni][1] = w.y;
    }

    const float inv_sqrt_d = 0.17677669529663687f;  // 1/sqrt(32)
    float* eout = out + EOUT_OFF;

    #pragma unroll
    for (int mi = 0; mi < 2; mi++)
        #pragma unroll
        for (int hh = 0; hh < 2; hh++) {
            int m = wm*32 + mi*16 + hh*8 + g;
            int e = e0 + m;
            int rn = ((int*)(sm + OFF_RN))[m];
            int cn = ((int*)(sm + OFF_CN))[m];
            float dist = ((float*)(sm + OFF_DIST))[m];
            float sum = 0.0f;
            #pragma unroll
            for (int ni = 0; ni < 4; ni++) {
                int c = cbase + ni*8;
                float2 q2 = *(const float2*)(g_q + (size_t)cn * 256 + c);
                float2 k2 = *(const float2*)(g_k + (size_t)rn * 256 + c);
                float ea0 = fmaf(dist, wl[ni][0], acc[mi][ni][hh*2+0]);
                float ea1 = fmaf(dist, wl[ni][1], acc[mi][ni][hh*2+1]);
                float t0 = fminf(5.0f, fmaxf(-5.0f, k2.x * q2.x * inv_sqrt_d));
                float t1 = fminf(5.0f, fmaxf(-5.0f, k2.y * q2.y * inv_sqrt_d));
                float a0 = t0 * ea0, a1 = t1 * ea1;
                *(float2*)(eout + (size_t)e * 256 + c) = make_float2(a0, a1);
                sum += a0 + a1;
            }
            sum += __shfl_xor_sync(0xffffffffu, sum, 1);
            sum += __shfl_xor_sync(0xffffffffu, sum, 2);
            if (quad == 0)
                g_ax[(size_t)e * HH + head] =
                    expf(fminf(5.0f, fmaxf(-5.0f, sum)));
        }
}

// ===========================================================================
// Gather + finalize: one block per destination node, no atomics.
// ===========================================================================
__global__ __launch_bounds__(256) void gather_kernel(
    const float* __restrict__ coords,
    float* __restrict__ out)
{
    __shared__ int se[256];
    __shared__ int sr[256];

    int n   = blockIdx.x;
    int tid = threadIdx.x;
    int h   = tid >> 5;

    int off = g_off[n];
    int end = g_off[n + 1];

    float acc  = 0.0f;
    float zacc = 0.0f;

    for (int base = off; base < end; base += 256) {
        int cnt = min(256, end - base);
        __syncthreads();
        for (int t = tid; t < cnt; t += 256) {
            int e = g_eid[base + t];
            se[t] = e;
            sr[t] = g_row[e];
        }
        __syncthreads();
        for (int j = 0; j < cnt; j++) {
            int e = se[j];
            int r = sr[j];
            float ax = g_ax[(size_t)e * HH + h];
            acc = fmaf(g_v[(size_t)r * HD + tid], ax, acc);
            if ((tid & 31) == 0) zacc += ax;
        }
    }

    float z = __shfl_sync(0xffffffffu, zacc, 0);
    out[(size_t)n * HD + tid] = acc / (z + 1e-6f);

    if (tid < 3) out[COORD_OFF + n*3 + tid] = coords[n*3 + tid];
}

// ===========================================================================
extern "C" void kernel_launch(void* const* d_in, const int* in_sizes, int n_in,
                              void* d_out, int out_size)
{
    const float* x         = (const float*)d_in[0];
    const float* edge_attr = (const float*)d_in[1];
    const void*  ei        = d_in[2];
    const float* coords    = (const float*)d_in[3];
    const float* Wq        = (const float*)d_in[4];
    const float* Wk        = (const float*)d_in[5];
    const float* Wv        = (const float*)d_in[6];
    const float* We        = (const float*)d_in[7];
    float* out = (float*)d_out;

    static int attr_done = 0;
    if (!attr_done) {
        cudaFuncSetAttribute(qkv_mma_kernel,
                             cudaFuncAttributeMaxDynamicSharedMemorySize, SMEM_TOT);
        cudaFuncSetAttribute(edge_mma_kernel,
                             cudaFuncAttributeMaxDynamicSharedMemorySize, SMEM_TOT);
        attr_done = 1;
    }

    zero_deg_kernel<<<(NN + 255) / 256, 256>>>();
    convert_hist_kernel<<<(EE + 255) / 256, 256>>>(ei);
    scanA_kernel<<<SCAN_BLOCKS, 256>>>();
    scanB_kernel<<<1, 64>>>();
    scanC_kernel<<<SCAN_BLOCKS, 256>>>();
    fill_kernel<<<(EE + 255) / 256, 256>>>();

    dim3 gtr(256, 4);
    wtrans_kernel<<<gtr, 256>>>(Wq, Wk, Wv, We);

    dim3 gqkv(250, 2, 3);
    qkv_mma_kernel<<<gqkv, 256, SMEM_TOT>>>(x);

    edge_mma_kernel<<<8000, 256, SMEM_TOT>>>(edge_attr, coords, We, out);

    gather_kernel<<<NN, 256>>>(coords, out);
}

// round 12
// speedup vs baseline: 1.3713x; 1.3713x over previous
#include <cuda_runtime.h>
#include <cuda_bf16.h>
#include <math.h>
#include <stdint.h>

#define NN 16000
#define EE 256000
#define DIN 256
#define HH 8
#define HD 256

#define EOUT_OFF  (NN * HD)             // 4,096,000
#define COORD_OFF (NN * HD + EE * HD)   // 69,632,000

// ---- scratch (static device globals; no runtime allocation) ----
__device__ float g_q[NN * HD];
__device__ float g_k[NN * HD];
__device__ float g_v[NN * HD];
__device__ float g_ax[EE * HH];
__device__ int   g_row[EE];
__device__ int   g_col[EE];
__device__ int   g_deg[NN];
__device__ int   g_off[NN + 1];
__device__ int   g_cursor[NN];
__device__ int   g_eid[EE];
__device__ int   g_bsum[64];
__device__ int   g_bsumx[64];
// transposed (K-major, [n*256+k]) bf16 hi/lo weights: mats 0..3 = Wq,Wk,Wv,We
__device__ __nv_bfloat16 g_bt_hi[4 * 65536];
__device__ __nv_bfloat16 g_bt_lo[4 * 65536];

// ===========================================================================
// MMA helpers (sm_80-baseline HMMA — compiles for plain sm_103)
// ===========================================================================
__device__ __forceinline__ uint32_t smem_u32(const void* p) {
    return (uint32_t)__cvta_generic_to_shared(p);
}

#define LDSM4(r, addr)                                                        \
    asm volatile("ldmatrix.sync.aligned.m8n8.x4.shared.b16 {%0,%1,%2,%3}, [%4];" \
        : "=r"((r)[0]), "=r"((r)[1]), "=r"((r)[2]), "=r"((r)[3]) : "r"(addr))

#define MMA16816(c, a, b0, b1)                                                \
    asm volatile("mma.sync.aligned.m16n8k16.row.col.f32.bf16.bf16.f32 "       \
        "{%0,%1,%2,%3}, {%4,%5,%6,%7}, {%8,%9}, {%0,%1,%2,%3};"               \
        : "+f"((c)[0]), "+f"((c)[1]), "+f"((c)[2]), "+f"((c)[3])              \
        : "r"((a)[0]), "r"((a)[1]), "r"((a)[2]), "r"((a)[3]),                 \
          "r"(b0), "r"(b1))

// SMEM layout (byte offsets into extern shared)
// A tile: 64 rows x 64 k bf16, stride 80 elems (160B) -> 10240 B each
// B tile: 128 rows x 64 k bf16, stride 80          -> 20480 B each
#define OFF_AHI   0u
#define OFF_ALO   10240u
#define OFF_BHI   20480u
#define OFF_BLO   40960u
#define OFF_DIST  61440u
#define OFF_RN    61696u
#define OFF_CN    61952u
#define SMEM_TOT  62208u

// ===========================================================================
// GEMM mainloop (round-9 proven form). Per thread acc[2][4][4] = fragment of
// D[64,128] = A[64,256] @ B[128,256]^T (bf16 hi/lo 3-pass).
// 8 warps: wm = wid&1 (32 rows), wn = wid>>1 (32 cols).
// Latency hiding comes from 2 CTAs/SM overlapping stage/compute phases.
// ===========================================================================
__device__ __forceinline__ void gemm_tile(
    char* sm, uint32_t sb,
    const float* __restrict__ Asrc,
    const __nv_bfloat16* __restrict__ bhi_g,
    const __nv_bfloat16* __restrict__ blo_g,
    int half, int tid, float acc[2][4][4])
{
    const int wid = tid >> 5, lane = tid & 31;
    const int wm = wid & 1, wn = wid >> 1;
    const uint32_t lrow = lane & 15;
    const uint32_t lkh  = ((lane >> 4) & 1) << 3;

    for (int chunk = 0; chunk < 4; chunk++) {
        const int k0 = chunk * 64;
        __syncthreads();

        // ---- stage A: fp32 -> bf16 hi/lo --------------------------------
        #pragma unroll
        for (int s = 0; s < 4; s++) {
            int idx = tid + s * 256;
            int r = idx >> 4, qd = idx & 15;
            float4 a = *(const float4*)(Asrc + (size_t)r * 256 + k0 + qd * 4);
            __nv_bfloat16 h0 = __float2bfloat16(a.x);
            __nv_bfloat16 h1 = __float2bfloat16(a.y);
            __nv_bfloat16 h2 = __float2bfloat16(a.z);
            __nv_bfloat16 h3 = __float2bfloat16(a.w);
            __nv_bfloat16 l0 = __float2bfloat16(a.x - __bfloat162float(h0));
            __nv_bfloat16 l1 = __float2bfloat16(a.y - __bfloat162float(h1));
            __nv_bfloat16 l2 = __float2bfloat16(a.z - __bfloat162float(h2));
            __nv_bfloat16 l3 = __float2bfloat16(a.w - __bfloat162float(h3));
            uint2 hv, lv;
            hv.x = ((uint32_t)__bfloat16_as_ushort(h1) << 16) | __bfloat16_as_ushort(h0);
            hv.y = ((uint32_t)__bfloat16_as_ushort(h3) << 16) | __bfloat16_as_ushort(h2);
            lv.x = ((uint32_t)__bfloat16_as_ushort(l1) << 16) | __bfloat16_as_ushort(l0);
            lv.y = ((uint32_t)__bfloat16_as_ushort(l3) << 16) | __bfloat16_as_ushort(l2);
            *(uint2*)(sm + OFF_AHI + r * 160 + qd * 8) = hv;
            *(uint2*)(sm + OFF_ALO + r * 160 + qd * 8) = lv;
        }

        // ---- stage B: copy precomputed hi/lo ----------------------------
        #pragma unroll
        for (int s = 0; s < 4; s++) {
            int idx = tid + s * 256;
            int n = idx >> 3, gq = idx & 7;
            size_t src = (size_t)(half * 128 + n) * 256 + k0 + gq * 8;
            *(uint4*)(sm + OFF_BHI + n * 160 + gq * 16) = *(const uint4*)(bhi_g + src);
            *(uint4*)(sm + OFF_BLO + n * 160 + gq * 16) = *(const uint4*)(blo_g + src);
        }
        __syncthreads();

        // ---- compute 4 k16 steps ---------------------------------------
        #pragma unroll
        for (int ks = 0; ks < 4; ks++) {
            const uint32_t koff = (uint32_t)(ks * 16 + lkh) * 2;
            uint32_t ah[2][4], al[2][4], bh[2][4], bl[2][4];
            #pragma unroll
            for (int mi = 0; mi < 2; mi++) {
                uint32_t addr = sb + OFF_AHI + (uint32_t)(wm*32 + mi*16 + lrow) * 160 + koff;
                LDSM4(ah[mi], addr);
                LDSM4(al[mi], addr + (OFF_ALO - OFF_AHI));
            }
            #pragma unroll
            for (int gj = 0; gj < 2; gj++) {
                uint32_t addr = sb + OFF_BHI + (uint32_t)(wn*32 + gj*16 + lrow) * 160 + koff;
                LDSM4(bh[gj], addr);
                LDSM4(bl[gj], addr + (OFF_BLO - OFF_BHI));
            }
            #pragma unroll
            for (int mi = 0; mi < 2; mi++)
                #pragma unroll
                for (int ni = 0; ni < 4; ni++) {
                    int gj = ni >> 1, up = ni & 1;
                    uint32_t b0h = bh[gj][up], b1h = bh[gj][up + 2];
                    uint32_t b0l = bl[gj][up], b1l = bl[gj][up + 2];
                    MMA16816(acc[mi][ni], ah[mi], b0h, b1h);
                    MMA16816(acc[mi][ni], ah[mi], b0l, b1l);
                    MMA16816(acc[mi][ni], al[mi], b0h, b1h);
                }
        }
    }
}

// ===========================================================================
// Preprocessing kernels
// ===========================================================================
__global__ void zero_deg_kernel() {
    int i = blockIdx.x * blockDim.x + threadIdx.x;
    if (i < NN) g_deg[i] = 0;
}

// Converts indices (self-detecting int64 vs int32) + destination histogram.
__global__ void convert_hist_kernel(const void* ei) {
    __shared__ int s_is64;
    if (threadIdx.x < 32) {
        const long long* p = (const long long*)ei;
        int bad = 0;
        for (int i = threadIdx.x; i < 512; i += 32) {
            long long v = p[i];
            if (v < 0 || v >= NN) bad = 1;
        }
        bad = __any_sync(0xffffffffu, bad);
        if (threadIdx.x == 0) s_is64 = bad ? 0 : 1;
    }
    __syncthreads();
    int i = blockIdx.x * blockDim.x + threadIdx.x;
    if (i < EE) {
        int r, c;
        if (s_is64) {
            const long long* p = (const long long*)ei;
            r = (int)p[i]; c = (int)p[EE + i];
        } else {
            const int* p = (const int*)ei;
            r = p[i]; c = p[EE + i];
        }
        g_row[i] = r; g_col[i] = c;
        atomicAdd(&g_deg[c], 1);
    }
}

// 3-phase multi-block exclusive scan of g_deg (16000 -> g_off, g_cursor).
#define SCAN_BLOCKS 63
__global__ void scanA_kernel() {
    __shared__ int s[256];
    int b = blockIdx.x, t = threadIdx.x;
    int i = b * 256 + t;
    int v = (i < NN) ? g_deg[i] : 0;
    s[t] = v;
    __syncthreads();
    #pragma unroll
    for (int off = 1; off < 256; off <<= 1) {
        int u = (t >= off) ? s[t - off] : 0;
        __syncthreads();
        s[t] += u;
        __syncthreads();
    }
    if (i < NN) g_off[i] = s[t] - v;   // block-local exclusive
    if (t == 255) g_bsum[b] = s[255];
}

__global__ void scanB_kernel() {
    __shared__ int s[SCAN_BLOCKS];
    int t = threadIdx.x;
    if (t < SCAN_BLOCKS) s[t] = g_bsum[t];
    __syncthreads();
    if (t == 0) {
        int run = 0;
        for (int b = 0; b < SCAN_BLOCKS; b++) {
            int v = s[b];
            s[b] = run;
            run += v;
        }
        g_off[NN] = run;
    }
    __syncthreads();
    if (t < SCAN_BLOCKS) g_bsumx[t] = s[t];
}

__global__ void scanC_kernel() {
    int b = blockIdx.x, t = threadIdx.x;
    int i = b * 256 + t;
    if (i < NN) {
        int o = g_off[i] + g_bsumx[b];
        g_off[i] = o;
        g_cursor[i] = o;
    }
}

__global__ void fill_kernel() {
    int i = blockIdx.x * blockDim.x + threadIdx.x;
    if (i < EE) {
        int c = g_col[i];
        int p = atomicAdd(&g_cursor[c], 1);
        g_eid[p] = i;
    }
}

// Transpose weights to K-major bf16 hi/lo. grid (256, 4)
__global__ void wtrans_kernel(const float* __restrict__ Wq, const float* __restrict__ Wk,
                              const float* __restrict__ Wv, const float* __restrict__ We) {
    int mat = blockIdx.y;
    const float* W = (mat == 0) ? Wq : (mat == 1) ? Wk : (mat == 2) ? Wv : We;
    int idx = blockIdx.x * 256 + threadIdx.x;
    int n = idx & 255;
    int k = idx >> 8;
    float v = W[(size_t)k * 256 + n];
    __nv_bfloat16 h = __float2bfloat16(v);
    __nv_bfloat16 l = __float2bfloat16(v - __bfloat162float(h));
    g_bt_hi[(size_t)mat * 65536 + (size_t)n * 256 + k] = h;
    g_bt_lo[(size_t)mat * 65536 + (size_t)n * 256 + k] = l;
}

// ===========================================================================
// q/k/v tensor-core GEMM. grid (250, 2, 3), 256 threads.
// ===========================================================================
__global__ __launch_bounds__(256, 2) void qkv_mma_kernel(const float* __restrict__ x) {
    extern __shared__ char sm[];
    uint32_t sb = smem_u32(sm);
    int tid = threadIdx.x;
    int m0   = blockIdx.x * 64;
    int half = blockIdx.y;
    int mat  = blockIdx.z;

    float acc[2][4][4] = {};
    gemm_tile(sm, sb, x + (size_t)m0 * 256,
              g_bt_hi + (size_t)mat * 65536, g_bt_lo + (size_t)mat * 65536,
              half, tid, acc);

    float* outp = (mat == 0) ? g_q : (mat == 1) ? g_k : g_v;
    int wid = tid >> 5, lane = tid & 31;
    int wm = wid & 1, wn = wid >> 1;
    int g = lane >> 2, quad = lane & 3;
    int cbase = half * 128 + wn * 32 + quad * 2;

    #pragma unroll
    for (int mi = 0; mi < 2; mi++)
        #pragma unroll
        for (int hh = 0; hh < 2; hh++) {
            int row = m0 + wm*32 + mi*16 + hh*8 + g;
            #pragma unroll
            for (int ni = 0; ni < 4; ni++)
                *(float2*)(outp + (size_t)row * 256 + cbase + ni*8) =
                    make_float2(acc[mi][ni][hh*2], acc[mi][ni][hh*2+1]);
        }
}

// ===========================================================================
// Edge GEMM + fused attention epilogue. grid 8000: tile = bid>>1,
// half = bid&1 so both halves of a tile are co-resident -> A tile L2 reuse.
// Warp wn covers exactly one head (32 cols) -> head sum is a quad shuffle.
// ===========================================================================
__global__ __launch_bounds__(256, 2) void edge_mma_kernel(
    const float* __restrict__ edge_attr,
    const float* __restrict__ coords,
    const float* __restrict__ We,
    float* __restrict__ out)
{
    extern __shared__ char sm[];
    uint32_t sb = smem_u32(sm);
    int tid = threadIdx.x;
    int e0   = (blockIdx.x >> 1) * 64;
    int half = blockIdx.x & 1;

    if (tid < 64) {
        int e = e0 + tid;
        int r = g_row[e], c = g_col[e];
        ((int*)(sm + OFF_RN))[tid] = r;
        ((int*)(sm + OFF_CN))[tid] = c;
        float dx = coords[r*3+0] - coords[c*3+0];
        float dy = coords[r*3+1] - coords[c*3+1];
        float dz = coords[r*3+2] - coords[c*3+2];
        ((float*)(sm + OFF_DIST))[tid] = 0.1f * sqrtf(dx*dx + dy*dy + dz*dz);
    }

    float acc[2][4][4] = {};
    gemm_tile(sm, sb, edge_attr + (size_t)e0 * 256,
              g_bt_hi + (size_t)3 * 65536, g_bt_lo + (size_t)3 * 65536,
              half, tid, acc);

    int wid = tid >> 5, lane = tid & 31;
    int wm = wid & 1, wn = wid >> 1;
    int g = lane >> 2, quad = lane & 3;
    int head  = half * 4 + wn;
    int cbase = half * 128 + wn * 32 + quad * 2;

    float wl[4][2];
    #pragma unroll
    for (int ni = 0; ni < 4; ni++) {
        float2 w = *(const float2*)(We + (size_t)256 * 256 + cbase + ni*8);
        wl[ni][0] = w.x; wl[ni][1] = w.y;
    }

    const float inv_sqrt_d = 0.17677669529663687f;  // 1/sqrt(32)
    float* eout = out + EOUT_OFF;

    #pragma unroll
    for (int mi = 0; mi < 2; mi++)
        #pragma unroll
        for (int hh = 0; hh < 2; hh++) {
            int m = wm*32 + mi*16 + hh*8 + g;
            int e = e0 + m;
            int rn = ((int*)(sm + OFF_RN))[m];
            int cn = ((int*)(sm + OFF_CN))[m];
            float dist = ((float*)(sm + OFF_DIST))[m];
            float sum = 0.0f;
            #pragma unroll
            for (int ni = 0; ni < 4; ni++) {
                int c = cbase + ni*8;
                float2 q2 = *(const float2*)(g_q + (size_t)cn * 256 + c);
                float2 k2 = *(const float2*)(g_k + (size_t)rn * 256 + c);
                float ea0 = fmaf(dist, wl[ni][0], acc[mi][ni][hh*2+0]);
                float ea1 = fmaf(dist, wl[ni][1], acc[mi][ni][hh*2+1]);
                float t0 = fminf(5.0f, fmaxf(-5.0f, k2.x * q2.x * inv_sqrt_d));
                float t1 = fminf(5.0f, fmaxf(-5.0f, k2.y * q2.y * inv_sqrt_d));
                float a0 = t0 * ea0, a1 = t1 * ea1;
                *(float2*)(eout + (size_t)e * 256 + c) = make_float2(a0, a1);
                sum += a0 + a1;
            }
            sum += __shfl_xor_sync(0xffffffffu, sum, 1);
            sum += __shfl_xor_sync(0xffffffffu, sum, 2);
            if (quad == 0)
                g_ax[(size_t)e * HH + head] =
                    expf(fminf(5.0f, fmaxf(-5.0f, sum)));
        }
}

// ===========================================================================
// Gather + finalize: one block per destination node, no atomics.
// ===========================================================================
__global__ __launch_bounds__(256) void gather_kernel(
    const float* __restrict__ coords,
    float* __restrict__ out)
{
    __shared__ int se[256];
    __shared__ int sr[256];

    int n   = blockIdx.x;
    int tid = threadIdx.x;
    int h   = tid >> 5;

    int off = g_off[n];
    int end = g_off[n + 1];

    float acc  = 0.0f;
    float zacc = 0.0f;

    for (int base = off; base < end; base += 256) {
        int cnt = min(256, end - base);
        __syncthreads();
        for (int t = tid; t < cnt; t += 256) {
            int e = g_eid[base + t];
            se[t] = e;
            sr[t] = g_row[e];
        }
        __syncthreads();
        #pragma unroll 4
        for (int j = 0; j < cnt; j++) {
            int e = se[j];
            int r = sr[j];
            float ax = g_ax[(size_t)e * HH + h];
            acc = fmaf(g_v[(size_t)r * HD + tid], ax, acc);
            if ((tid & 31) == 0) zacc += ax;
        }
    }

    float z = __shfl_sync(0xffffffffu, zacc, 0);
    out[(size_t)n * HD + tid] = acc / (z + 1e-6f);

    if (tid < 3) out[COORD_OFF + n*3 + tid] = coords[n*3 + tid];
}

// ===========================================================================
extern "C" void kernel_launch(void* const* d_in, const int* in_sizes, int n_in,
                              void* d_out, int out_size)
{
    const float* x         = (const float*)d_in[0];
    const float* edge_attr = (const float*)d_in[1];
    const void*  ei        = d_in[2];
    const float* coords    = (const float*)d_in[3];
    const float* Wq        = (const float*)d_in[4];
    const float* Wk        = (const float*)d_in[5];
    const float* Wv        = (const float*)d_in[6];
    const float* We        = (const float*)d_in[7];
    float* out = (float*)d_out;

    static int attr_done = 0;
    if (!attr_done) {
        cudaFuncSetAttribute(qkv_mma_kernel,
                             cudaFuncAttributeMaxDynamicSharedMemorySize, SMEM_TOT);
        cudaFuncSetAttribute(edge_mma_kernel,
                             cudaFuncAttributeMaxDynamicSharedMemorySize, SMEM_TOT);
        attr_done = 1;
    }

    zero_deg_kernel<<<(NN + 255) / 256, 256>>>();
    convert_hist_kernel<<<(EE + 255) / 256, 256>>>(ei);
    scanA_kernel<<<SCAN_BLOCKS, 256>>>();
    scanB_kernel<<<1, 64>>>();
    scanC_kernel<<<SCAN_BLOCKS, 256>>>();
    fill_kernel<<<(EE + 255) / 256, 256>>>();

    dim3 gtr(256, 4);
    wtrans_kernel<<<gtr, 256>>>(Wq, Wk, Wv, We);

    dim3 gqkv(250, 2, 3);
    qkv_mma_kernel<<<gqkv, 256, SMEM_TOT>>>(x);

    edge_mma_kernel<<<8000, 256, SMEM_TOT>>>(edge_attr, coords, We, out);

    gather_kernel<<<NN, 256>>>(coords, out);
}

// round 14
// speedup vs baseline: 1.3969x; 1.0187x over previous
#include <cuda_runtime.h>
#include <cuda_bf16.h>
#include <math.h>
#include <stdint.h>

#define NN 16000
#define EE 256000
#define DIN 256
#define HH 8
#define HD 256

#define EOUT_OFF  (NN * HD)             // 4,096,000
#define COORD_OFF (NN * HD + EE * HD)   // 69,632,000

// ---- scratch (static device globals; no runtime allocation) ----
__device__ float g_q[NN * HD];
__device__ float g_k[NN * HD];
__device__ float g_v[NN * HD];
__device__ float g_ax[EE * HH];
__device__ int   g_row[EE];
__device__ int   g_col[EE];
__device__ int   g_deg[NN];
__device__ int   g_off[NN + 1];
__device__ int   g_cursor[NN];
__device__ int   g_eid[EE];
__device__ int   g_bsum[64];
// transposed (K-major, [n*256+k]) bf16 hi/lo weights: mats 0..3 = Wq,Wk,Wv,We
__device__ __nv_bfloat16 g_bt_hi[4 * 65536];
__device__ __nv_bfloat16 g_bt_lo[4 * 65536];

// ===========================================================================
// MMA helpers (sm_80-baseline HMMA — compiles for plain sm_103)
// ===========================================================================
__device__ __forceinline__ uint32_t smem_u32(const void* p) {
    return (uint32_t)__cvta_generic_to_shared(p);
}

#define LDSM4(r, addr)                                                        \
    asm volatile("ldmatrix.sync.aligned.m8n8.x4.shared.b16 {%0,%1,%2,%3}, [%4];" \
        : "=r"((r)[0]), "=r"((r)[1]), "=r"((r)[2]), "=r"((r)[3]) : "r"(addr))

#define MMA16816(c, a, b0, b1)                                                \
    asm volatile("mma.sync.aligned.m16n8k16.row.col.f32.bf16.bf16.f32 "       \
        "{%0,%1,%2,%3}, {%4,%5,%6,%7}, {%8,%9}, {%0,%1,%2,%3};"               \
        : "+f"((c)[0]), "+f"((c)[1]), "+f"((c)[2]), "+f"((c)[3])              \
        : "r"((a)[0]), "r"((a)[1]), "r"((a)[2]), "r"((a)[3]),                 \
          "r"(b0), "r"(b1))

// SMEM layout (byte offsets into extern shared)
// A tile: 64 rows x 64 k bf16, stride 80 elems (160B) -> 10240 B each
// B tile: 128 rows x 64 k bf16, stride 80          -> 20480 B each
#define OFF_AHI   0u
#define OFF_ALO   10240u
#define OFF_BHI   20480u
#define OFF_BLO   40960u
#define OFF_DIST  61440u
#define OFF_RN    61696u
#define OFF_CN    61952u
#define SMEM_TOT  62208u

// ===========================================================================
// GEMM mainloop (round-9 proven form). Per thread acc[2][4][4] = fragment of
// D[64,128] = A[64,256] @ B[128,256]^T (bf16 hi/lo 3-pass).
// 8 warps: wm = wid&1 (32 rows), wn = wid>>1 (32 cols).
// Latency hiding comes from 2 CTAs/SM overlapping stage/compute phases.
// ===========================================================================
__device__ __forceinline__ void gemm_tile(
    char* sm, uint32_t sb,
    const float* __restrict__ Asrc,
    const __nv_bfloat16* __restrict__ bhi_g,
    const __nv_bfloat16* __restrict__ blo_g,
    int half, int tid, float acc[2][4][4])
{
    const int wid = tid >> 5, lane = tid & 31;
    const int wm = wid & 1, wn = wid >> 1;
    const uint32_t lrow = lane & 15;
    const uint32_t lkh  = ((lane >> 4) & 1) << 3;

    for (int chunk = 0; chunk < 4; chunk++) {
        const int k0 = chunk * 64;
        __syncthreads();

        // ---- stage A: fp32 -> bf16 hi/lo --------------------------------
        #pragma unroll
        for (int s = 0; s < 4; s++) {
            int idx = tid + s * 256;
            int r = idx >> 4, qd = idx & 15;
            float4 a = *(const float4*)(Asrc + (size_t)r * 256 + k0 + qd * 4);
            __nv_bfloat16 h0 = __float2bfloat16(a.x);
            __nv_bfloat16 h1 = __float2bfloat16(a.y);
            __nv_bfloat16 h2 = __float2bfloat16(a.z);
            __nv_bfloat16 h3 = __float2bfloat16(a.w);
            __nv_bfloat16 l0 = __float2bfloat16(a.x - __bfloat162float(h0));
            __nv_bfloat16 l1 = __float2bfloat16(a.y - __bfloat162float(h1));
            __nv_bfloat16 l2 = __float2bfloat16(a.z - __bfloat162float(h2));
            __nv_bfloat16 l3 = __float2bfloat16(a.w - __bfloat162float(h3));
            uint2 hv, lv;
            hv.x = ((uint32_t)__bfloat16_as_ushort(h1) << 16) | __bfloat16_as_ushort(h0);
            hv.y = ((uint32_t)__bfloat16_as_ushort(h3) << 16) | __bfloat16_as_ushort(h2);
            lv.x = ((uint32_t)__bfloat16_as_ushort(l1) << 16) | __bfloat16_as_ushort(l0);
            lv.y = ((uint32_t)__bfloat16_as_ushort(l3) << 16) | __bfloat16_as_ushort(l2);
            *(uint2*)(sm + OFF_AHI + r * 160 + qd * 8) = hv;
            *(uint2*)(sm + OFF_ALO + r * 160 + qd * 8) = lv;
        }

        // ---- stage B: copy precomputed hi/lo ----------------------------
        #pragma unroll
        for (int s = 0; s < 4; s++) {
            int idx = tid + s * 256;
            int n = idx >> 3, gq = idx & 7;
            size_t src = (size_t)(half * 128 + n) * 256 + k0 + gq * 8;
            *(uint4*)(sm + OFF_BHI + n * 160 + gq * 16) = *(const uint4*)(bhi_g + src);
            *(uint4*)(sm + OFF_BLO + n * 160 + gq * 16) = *(const uint4*)(blo_g + src);
        }
        __syncthreads();

        // ---- compute 4 k16 steps ---------------------------------------
        #pragma unroll
        for (int ks = 0; ks < 4; ks++) {
            const uint32_t koff = (uint32_t)(ks * 16 + lkh) * 2;
            uint32_t ah[2][4], al[2][4], bh[2][4], bl[2][4];
            #pragma unroll
            for (int mi = 0; mi < 2; mi++) {
                uint32_t addr = sb + OFF_AHI + (uint32_t)(wm*32 + mi*16 + lrow) * 160 + koff;
                LDSM4(ah[mi], addr);
                LDSM4(al[mi], addr + (OFF_ALO - OFF_AHI));
            }
            #pragma unroll
            for (int gj = 0; gj < 2; gj++) {
                uint32_t addr = sb + OFF_BHI + (uint32_t)(wn*32 + gj*16 + lrow) * 160 + koff;
                LDSM4(bh[gj], addr);
                LDSM4(bl[gj], addr + (OFF_BLO - OFF_BHI));
            }
            #pragma unroll
            for (int mi = 0; mi < 2; mi++)
                #pragma unroll
                for (int ni = 0; ni < 4; ni++) {
                    int gj = ni >> 1, up = ni & 1;
                    uint32_t b0h = bh[gj][up], b1h = bh[gj][up + 2];
                    uint32_t b0l = bl[gj][up], b1l = bl[gj][up + 2];
                    MMA16816(acc[mi][ni], ah[mi], b0h, b1h);
                    MMA16816(acc[mi][ni], ah[mi], b0l, b1l);
                    MMA16816(acc[mi][ni], al[mi], b0h, b1h);
                }
        }
    }
}

// ===========================================================================
// Preprocessing kernels
// ===========================================================================
__global__ void zero_deg_kernel() {
    int i = blockIdx.x * blockDim.x + threadIdx.x;
    if (i < NN) g_deg[i] = 0;
}

// Converts indices (self-detecting int64 vs int32) + destination histogram.
__global__ void convert_hist_kernel(const void* ei) {
    __shared__ int s_is64;
    if (threadIdx.x < 32) {
        const long long* p = (const long long*)ei;
        int bad = 0;
        for (int i = threadIdx.x; i < 512; i += 32) {
            long long v = p[i];
            if (v < 0 || v >= NN) bad = 1;
        }
        bad = __any_sync(0xffffffffu, bad);
        if (threadIdx.x == 0) s_is64 = bad ? 0 : 1;
    }
    __syncthreads();
    int i = blockIdx.x * blockDim.x + threadIdx.x;
    if (i < EE) {
        int r, c;
        if (s_is64) {
            const long long* p = (const long long*)ei;
            r = (int)p[i]; c = (int)p[EE + i];
        } else {
            const int* p = (const int*)ei;
            r = p[i]; c = p[EE + i];
        }
        g_row[i] = r; g_col[i] = c;
        atomicAdd(&g_deg[c], 1);
    }
}

// 2-phase multi-block exclusive scan of g_deg (16000 -> g_off, g_cursor).
#define SCAN_BLOCKS 63
__global__ void scanA_kernel() {
    __shared__ int s[256];
    int b = blockIdx.x, t = threadIdx.x;
    int i = b * 256 + t;
    int v = (i < NN) ? g_deg[i] : 0;
    s[t] = v;
    __syncthreads();
    #pragma unroll
    for (int off = 1; off < 256; off <<= 1) {
        int u = (t >= off) ? s[t - off] : 0;
        __syncthreads();
        s[t] += u;
        __syncthreads();
    }
    if (i < NN) g_off[i] = s[t] - v;   // block-local exclusive
    if (t == 255) g_bsum[b] = s[255];
}

// Each block redoes the tiny 63-element block-sum scan (cheap) + applies it.
__global__ void scanC_kernel() {
    __shared__ int s[64];
    int b = blockIdx.x, t = threadIdx.x;
    if (t < 64) s[t] = (t < SCAN_BLOCKS) ? g_bsum[t] : 0;
    __syncthreads();
    #pragma unroll
    for (int off = 1; off < 64; off <<= 1) {
        int u = (t >= off && t < 64) ? s[t - off] : 0;
        __syncthreads();
        if (t < 64) s[t] += u;
        __syncthreads();
    }
    // s is now inclusive scan of block sums
    int pref = (b == 0) ? 0 : s[b - 1];
    int i = b * 256 + t;
    if (i < NN) {
        int o = g_off[i] + pref;
        g_off[i] = o;
        g_cursor[i] = o;
    }
    if (b == 0 && t == 0) g_off[NN] = s[SCAN_BLOCKS - 1];
}

__global__ void fill_kernel() {
    int i = blockIdx.x * blockDim.x + threadIdx.x;
    if (i < EE) {
        int c = g_col[i];
        int p = atomicAdd(&g_cursor[c], 1);
        g_eid[p] = i;
    }
}

// Transpose weights to K-major bf16 hi/lo. grid (256, 4)
__global__ void wtrans_kernel(const float* __restrict__ Wq, const float* __restrict__ Wk,
                              const float* __restrict__ Wv, const float* __restrict__ We) {
    int mat = blockIdx.y;
    const float* W = (mat == 0) ? Wq : (mat == 1) ? Wk : (mat == 2) ? Wv : We;
    int idx = blockIdx.x * 256 + threadIdx.x;
    int n = idx & 255;
    int k = idx >> 8;
    float v = W[(size_t)k * 256 + n];
    __nv_bfloat16 h = __float2bfloat16(v);
    __nv_bfloat16 l = __float2bfloat16(v - __bfloat162float(h));
    g_bt_hi[(size_t)mat * 65536 + (size_t)n * 256 + k] = h;
    g_bt_lo[(size_t)mat * 65536 + (size_t)n * 256 + k] = l;
}

// ===========================================================================
// q/k/v tensor-core GEMM. grid (250, 2, 3), 256 threads.
// ===========================================================================
__global__ __launch_bounds__(256, 2) void qkv_mma_kernel(const float* __restrict__ x) {
    extern __shared__ char sm[];
    uint32_t sb = smem_u32(sm);
    int tid = threadIdx.x;
    int m0   = blockIdx.x * 64;
    int half = blockIdx.y;
    int mat  = blockIdx.z;

    float acc[2][4][4] = {};
    gemm_tile(sm, sb, x + (size_t)m0 * 256,
              g_bt_hi + (size_t)mat * 65536, g_bt_lo + (size_t)mat * 65536,
              half, tid, acc);

    float* outp = (mat == 0) ? g_q : (mat == 1) ? g_k : g_v;
    int wid = tid >> 5, lane = tid & 31;
    int wm = wid & 1, wn = wid >> 1;
    int g = lane >> 2, quad = lane & 3;
    int cbase = half * 128 + wn * 32 + quad * 2;

    #pragma unroll
    for (int mi = 0; mi < 2; mi++)
        #pragma unroll
        for (int hh = 0; hh < 2; hh++) {
            int row = m0 + wm*32 + mi*16 + hh*8 + g;
            #pragma unroll
            for (int ni = 0; ni < 4; ni++)
                *(float2*)(outp + (size_t)row * 256 + cbase + ni*8) =
                    make_float2(acc[mi][ni][hh*2], acc[mi][ni][hh*2+1]);
        }
}

// ===========================================================================
// Edge GEMM + fused attention epilogue. grid 8000: tile = bid>>1,
// half = bid&1 so both halves of a tile are co-resident -> A tile L2 reuse.
// Warp wn covers exactly one head (32 cols) -> head sum is a quad shuffle.
// ===========================================================================
__global__ __launch_bounds__(256, 2) void edge_mma_kernel(
    const float* __restrict__ edge_attr,
    const float* __restrict__ coords,
    const float* __restrict__ We,
    float* __restrict__ out)
{
    extern __shared__ char sm[];
    uint32_t sb = smem_u32(sm);
    int tid = threadIdx.x;
    int e0   = (blockIdx.x >> 1) * 64;
    int half = blockIdx.x & 1;

    if (tid < 64) {
        int e = e0 + tid;
        int r = g_row[e], c = g_col[e];
        ((int*)(sm + OFF_RN))[tid] = r;
        ((int*)(sm + OFF_CN))[tid] = c;
        float dx = coords[r*3+0] - coords[c*3+0];
        float dy = coords[r*3+1] - coords[c*3+1];
        float dz = coords[r*3+2] - coords[c*3+2];
        ((float*)(sm + OFF_DIST))[tid] = 0.1f * sqrtf(dx*dx + dy*dy + dz*dz);
    }

    float acc[2][4][4] = {};
    gemm_tile(sm, sb, edge_attr + (size_t)e0 * 256,
              g_bt_hi + (size_t)3 * 65536, g_bt_lo + (size_t)3 * 65536,
              half, tid, acc);

    int wid = tid >> 5, lane = tid & 31;
    int wm = wid & 1, wn = wid >> 1;
    int g = lane >> 2, quad = lane & 3;
    int head  = half * 4 + wn;
    int cbase = half * 128 + wn * 32 + quad * 2;

    float wl[4][2];
    #pragma unroll
    for (int ni = 0; ni < 4; ni++) {
        float2 w = *(const float2*)(We + (size_t)256 * 256 + cbase + ni*8);
        wl[ni][0] = w.x; wl[ni][1] = w.y;
    }

    const float inv_sqrt_d = 0.17677669529663687f;  // 1/sqrt(32)
    float* eout = out + EOUT_OFF;

    #pragma unroll
    for (int mi = 0; mi < 2; mi++)
        #pragma unroll
        for (int hh = 0; hh < 2; hh++) {
            int m = wm*32 + mi*16 + hh*8 + g;
            int e = e0 + m;
            int rn = ((int*)(sm + OFF_RN))[m];
            int cn = ((int*)(sm + OFF_CN))[m];
            float dist = ((float*)(sm + OFF_DIST))[m];
            float sum = 0.0f;
            #pragma unroll
            for (int ni = 0; ni < 4; ni++) {
                int c = cbase + ni*8;
                float2 q2 = *(const float2*)(g_q + (size_t)cn * 256 + c);
                float2 k2 = *(const float2*)(g_k + (size_t)rn * 256 + c);
                float ea0 = fmaf(dist, wl[ni][0], acc[mi][ni][hh*2+0]);
                float ea1 = fmaf(dist, wl[ni][1], acc[mi][ni][hh*2+1]);
                float t0 = fminf(5.0f, fmaxf(-5.0f, k2.x * q2.x * inv_sqrt_d));
                float t1 = fminf(5.0f, fmaxf(-5.0f, k2.y * q2.y * inv_sqrt_d));
                float a0 = t0 * ea0, a1 = t1 * ea1;
                *(float2*)(eout + (size_t)e * 256 + c) = make_float2(a0, a1);
                sum += a0 + a1;
            }
            sum += __shfl_xor_sync(0xffffffffu, sum, 1);
            sum += __shfl_xor_sync(0xffffffffu, sum, 2);
            if (quad == 0)
                g_ax[(size_t)e * HH + head] =
                    expf(fminf(5.0f, fmaxf(-5.0f, sum)));
        }
}

// ===========================================================================
// Gather + finalize: one block per destination node, no atomics.
// g_ax staged to smem so the inner loop's only global load is the coalesced
// g_v row (unroll 8 -> MLP 8).
// ===========================================================================
__global__ __launch_bounds__(256) void gather_kernel(
    const float* __restrict__ coords,
    float* __restrict__ out)
{
    __shared__ int   sr[256];
    __shared__ float sax[256 * HH];

    int n   = blockIdx.x;
    int tid = threadIdx.x;
    int h   = tid >> 5;

    int off = g_off[n];
    int end = g_off[n + 1];

    float acc  = 0.0f;
    float zacc = 0.0f;   // valid on lane 0 of each warp

    for (int base = off; base < end; base += 256) {
        int cnt = min(256, end - base);
        __syncthreads();
        for (int t = tid; t < cnt; t += 256)
            sr[t] = g_row[g_eid[base + t]];
        for (int t = tid; t < cnt * HH; t += 256) {
            int e = g_eid[base + (t >> 3)];
            sax[t] = g_ax[(size_t)e * HH + (t & 7)];
        }
        __syncthreads();
        #pragma unroll 8
        for (int j = 0; j < cnt; j++)
            acc = fmaf(g_v[(size_t)sr[j] * HD + tid], sax[j * HH + h], acc);
        if ((tid & 31) == 0)
            for (int j = 0; j < cnt; j++) zacc += sax[j * HH + h];
    }

    float z = __shfl_sync(0xffffffffu, zacc, 0);
    out[(size_t)n * HD + tid] = acc / (z + 1e-6f);

    if (tid < 3) out[COORD_OFF + n*3 + tid] = coords[n*3 + tid];
}

// ===========================================================================
extern "C" void kernel_launch(void* const* d_in, const int* in_sizes, int n_in,
                              void* d_out, int out_size)
{
    const float* x         = (const float*)d_in[0];
    const float* edge_attr = (const float*)d_in[1];
    const void*  ei        = d_in[2];
    const float* coords    = (const float*)d_in[3];
    const float* Wq        = (const float*)d_in[4];
    const float* Wk        = (const float*)d_in[5];
    const float* Wv        = (const float*)d_in[6];
    const float* We        = (const float*)d_in[7];
    float* out = (float*)d_out;

    static cudaStream_t s2 = nullptr;
    static cudaEvent_t  e_fork = nullptr, e_conv = nullptr, e_fill = nullptr;
    if (!s2) {
        cudaFuncSetAttribute(qkv_mma_kernel,
                             cudaFuncAttributeMaxDynamicSharedMemorySize, SMEM_TOT);
        cudaFuncSetAttribute(edge_mma_kernel,
                             cudaFuncAttributeMaxDynamicSharedMemorySize, SMEM_TOT);
        cudaStreamCreateWithFlags(&s2, cudaStreamNonBlocking);
        cudaEventCreateWithFlags(&e_fork, cudaEventDisableTiming);
        cudaEventCreateWithFlags(&e_conv, cudaEventDisableTiming);
        cudaEventCreateWithFlags(&e_fill, cudaEventDisableTiming);
    }

    // ---- fork: CSR preprocessing chain on s2 ----------------------------
    cudaEventRecord(e_fork, 0);
    cudaStreamWaitEvent(s2, e_fork, 0);

    zero_deg_kernel<<<(NN + 255) / 256, 256, 0, s2>>>();
    convert_hist_kernel<<<(EE + 255) / 256, 256, 0, s2>>>(ei);
    cudaEventRecord(e_conv, s2);
    scanA_kernel<<<SCAN_BLOCKS, 256, 0, s2>>>();
    scanC_kernel<<<SCAN_BLOCKS, 256, 0, s2>>>();
    fill_kernel<<<(EE + 255) / 256, 256, 0, s2>>>();
    cudaEventRecord(e_fill, s2);

    // ---- main stream: weights + qkv (independent of edge_index) ---------
    dim3 gtr(256, 4);
    wtrans_kernel<<<gtr, 256>>>(Wq, Wk, Wv, We);

    dim3 gqkv(250, 2, 3);
    qkv_mma_kernel<<<gqkv, 256, SMEM_TOT>>>(x);

    // edge needs g_row/g_col (convert) + qkv + wtrans
    cudaStreamWaitEvent(0, e_conv, 0);
    edge_mma_kernel<<<8000, 256, SMEM_TOT>>>(edge_attr, coords, We, out);

    // gather needs CSR (fill) + g_ax (edge)
    cudaStreamWaitEvent(0, e_fill, 0);
    gather_kernel<<<NN, 256>>>(coords, out);
}

// round 17
// speedup vs baseline: 1.5772x; 1.1291x over previous
#include <cuda_runtime.h>
#include <cuda_bf16.h>
#include <cuda_fp16.h>
#include <math.h>
#include <stdint.h>

#define NN 16000
#define EE 256000
#define DIN 256
#define HH 8
#define HD 256

#define EOUT_OFF  (NN * HD)             // 4,096,000
#define COORD_OFF (NN * HD + EE * HD)   // 69,632,000

// ---- scratch (static device globals; no runtime allocation) ----
__device__ float g_q[NN * HD];
__device__ float g_k[NN * HD];
__device__ float g_v[NN * HD];
__device__ float g_ax[EE * HH];
__device__ int   g_row[EE];
__device__ int   g_col[EE];
__device__ int   g_deg[NN];
__device__ int   g_off[NN + 1];
__device__ int   g_cursor[NN];
__device__ int   g_eid[EE];
__device__ int   g_bsum[64];
// transposed (K-major, [n*256+k]) bf16 hi/lo weights: mats 0..2 = Wq,Wk,Wv
__device__ __nv_bfloat16 g_bt_hi[3 * 65536];
__device__ __nv_bfloat16 g_bt_lo[3 * 65536];
// We transposed K-major, single fp16 (edge GEMM B operand)
__device__ __half g_we_h[65536];

// ===========================================================================
// MMA helpers (sm_80-baseline HMMA — compiles for plain sm_103)
// ===========================================================================
__device__ __forceinline__ uint32_t smem_u32(const void* p) {
    return (uint32_t)__cvta_generic_to_shared(p);
}

#define LDSM4(r, addr)                                                        \
    asm volatile("ldmatrix.sync.aligned.m8n8.x4.shared.b16 {%0,%1,%2,%3}, [%4];" \
        : "=r"((r)[0]), "=r"((r)[1]), "=r"((r)[2]), "=r"((r)[3]) : "r"(addr))

#define MMA16816(c, a, b0, b1)                                                \
    asm volatile("mma.sync.aligned.m16n8k16.row.col.f32.bf16.bf16.f32 "       \
        "{%0,%1,%2,%3}, {%4,%5,%6,%7}, {%8,%9}, {%0,%1,%2,%3};"               \
        : "+f"((c)[0]), "+f"((c)[1]), "+f"((c)[2]), "+f"((c)[3])              \
        : "r"((a)[0]), "r"((a)[1]), "r"((a)[2]), "r"((a)[3]),                 \
          "r"(b0), "r"(b1))

#define MMA16816H(c, a, b0, b1)                                               \
    asm volatile("mma.sync.aligned.m16n8k16.row.col.f32.f16.f16.f32 "         \
        "{%0,%1,%2,%3}, {%4,%5,%6,%7}, {%8,%9}, {%0,%1,%2,%3};"               \
        : "+f"((c)[0]), "+f"((c)[1]), "+f"((c)[2]), "+f"((c)[3])              \
        : "r"((a)[0]), "r"((a)[1]), "r"((a)[2]), "r"((a)[3]),                 \
          "r"(b0), "r"(b1))

// --- bf16 kernel smem layout (qkv) ---
#define OFF_AHI   0u
#define OFF_ALO   10240u
#define OFF_BHI   20480u
#define OFF_BLO   40960u
#define SMEM_QKV  61440u
// --- fp16 edge kernel smem layout ---
#define EOFF_AHI  0u
#define EOFF_ALO  10240u
#define EOFF_B    20480u
#define EOFF_DIST 40960u
#define EOFF_RN   41216u
#define EOFF_CN   41472u
#define SMEM_EDGE 41728u

// ===========================================================================
// bf16 3-pass GEMM mainloop (qkv; round-9 proven form).
// acc[2][4][4] = fragment of D[64,128] = A[64,256] @ B[128,256]^T.
// ===========================================================================
__device__ __forceinline__ void gemm_tile_bf16(
    char* sm, uint32_t sb,
    const float* __restrict__ Asrc,
    const __nv_bfloat16* __restrict__ bhi_g,
    const __nv_bfloat16* __restrict__ blo_g,
    int half, int tid, float acc[2][4][4])
{
    const int wid = tid >> 5, lane = tid & 31;
    const int wm = wid & 1, wn = wid >> 1;
    const uint32_t lrow = lane & 15;
    const uint32_t lkh  = ((lane >> 4) & 1) << 3;

    for (int chunk = 0; chunk < 4; chunk++) {
        const int k0 = chunk * 64;
        __syncthreads();

        #pragma unroll
        for (int s = 0; s < 4; s++) {
            int idx = tid + s * 256;
            int r = idx >> 4, qd = idx & 15;
            float4 a = *(const float4*)(Asrc + (size_t)r * 256 + k0 + qd * 4);
            __nv_bfloat16 h0 = __float2bfloat16(a.x);
            __nv_bfloat16 h1 = __float2bfloat16(a.y);
            __nv_bfloat16 h2 = __float2bfloat16(a.z);
            __nv_bfloat16 h3 = __float2bfloat16(a.w);
            __nv_bfloat16 l0 = __float2bfloat16(a.x - __bfloat162float(h0));
            __nv_bfloat16 l1 = __float2bfloat16(a.y - __bfloat162float(h1));
            __nv_bfloat16 l2 = __float2bfloat16(a.z - __bfloat162float(h2));
            __nv_bfloat16 l3 = __float2bfloat16(a.w - __bfloat162float(h3));
            uint2 hv, lv;
            hv.x = ((uint32_t)__bfloat16_as_ushort(h1) << 16) | __bfloat16_as_ushort(h0);
            hv.y = ((uint32_t)__bfloat16_as_ushort(h3) << 16) | __bfloat16_as_ushort(h2);
            lv.x = ((uint32_t)__bfloat16_as_ushort(l1) << 16) | __bfloat16_as_ushort(l0);
            lv.y = ((uint32_t)__bfloat16_as_ushort(l3) << 16) | __bfloat16_as_ushort(l2);
            *(uint2*)(sm + OFF_AHI + r * 160 + qd * 8) = hv;
            *(uint2*)(sm + OFF_ALO + r * 160 + qd * 8) = lv;
        }

        #pragma unroll
        for (int s = 0; s < 4; s++) {
            int idx = tid + s * 256;
            int n = idx >> 3, gq = idx & 7;
            size_t src = (size_t)(half * 128 + n) * 256 + k0 + gq * 8;
            *(uint4*)(sm + OFF_BHI + n * 160 + gq * 16) = *(const uint4*)(bhi_g + src);
            *(uint4*)(sm + OFF_BLO + n * 160 + gq * 16) = *(const uint4*)(blo_g + src);
        }
        __syncthreads();

        #pragma unroll
        for (int ks = 0; ks < 4; ks++) {
            const uint32_t koff = (uint32_t)(ks * 16 + lkh) * 2;
            uint32_t ah[2][4], al[2][4], bh[2][4], bl[2][4];
            #pragma unroll
            for (int mi = 0; mi < 2; mi++) {
                uint32_t addr = sb + OFF_AHI + (uint32_t)(wm*32 + mi*16 + lrow) * 160 + koff;
                LDSM4(ah[mi], addr);
                LDSM4(al[mi], addr + (OFF_ALO - OFF_AHI));
            }
            #pragma unroll
            for (int gj = 0; gj < 2; gj++) {
                uint32_t addr = sb + OFF_BHI + (uint32_t)(wn*32 + gj*16 + lrow) * 160 + koff;
                LDSM4(bh[gj], addr);
                LDSM4(bl[gj], addr + (OFF_BLO - OFF_BHI));
            }
            #pragma unroll
            for (int mi = 0; mi < 2; mi++)
                #pragma unroll
                for (int ni = 0; ni < 4; ni++) {
                    int gj = ni >> 1, up = ni & 1;
                    uint32_t b0h = bh[gj][up], b1h = bh[gj][up + 2];
                    uint32_t b0l = bl[gj][up], b1l = bl[gj][up + 2];
                    MMA16816(acc[mi][ni], ah[mi], b0h, b1h);
                    MMA16816(acc[mi][ni], ah[mi], b0l, b1l);
                    MMA16816(acc[mi][ni], al[mi], b0h, b1h);
                }
        }
    }
}

// ===========================================================================
// fp16 2-pass GEMM mainloop (edge): A split hi/lo inline (captures edge_attr
// to 2^-22), B = single fp16 weights. Error dominated by B rep (~2.8e-4).
// ===========================================================================
__device__ __forceinline__ void gemm_tile_f16(
    char* sm, uint32_t sb,
    const float* __restrict__ Asrc,
    const __half* __restrict__ b_g,
    int half, int tid, float acc[2][4][4])
{
    const int wid = tid >> 5, lane = tid & 31;
    const int wm = wid & 1, wn = wid >> 1;
    const uint32_t lrow = lane & 15;
    const uint32_t lkh  = ((lane >> 4) & 1) << 3;

    for (int chunk = 0; chunk < 4; chunk++) {
        const int k0 = chunk * 64;
        __syncthreads();

        // ---- stage A: fp32 -> fp16 hi/lo --------------------------------
        #pragma unroll
        for (int s = 0; s < 4; s++) {
            int idx = tid + s * 256;
            int r = idx >> 4, qd = idx & 15;
            float4 a = *(const float4*)(Asrc + (size_t)r * 256 + k0 + qd * 4);
            __half h0 = __float2half(a.x);
            __half h1 = __float2half(a.y);
            __half h2 = __float2half(a.z);
            __half h3 = __float2half(a.w);
            __half l0 = __float2half(a.x - __half2float(h0));
            __half l1 = __float2half(a.y - __half2float(h1));
            __half l2 = __float2half(a.z - __half2float(h2));
            __half l3 = __float2half(a.w - __half2float(h3));
            uint2 hv, lv;
            hv.x = ((uint32_t)__half_as_ushort(h1) << 16) | __half_as_ushort(h0);
            hv.y = ((uint32_t)__half_as_ushort(h3) << 16) | __half_as_ushort(h2);
            lv.x = ((uint32_t)__half_as_ushort(l1) << 16) | __half_as_ushort(l0);
            lv.y = ((uint32_t)__half_as_ushort(l3) << 16) | __half_as_ushort(l2);
            *(uint2*)(sm + EOFF_AHI + r * 160 + qd * 8) = hv;
            *(uint2*)(sm + EOFF_ALO + r * 160 + qd * 8) = lv;
        }

        // ---- stage B: single fp16 ---------------------------------------
        #pragma unroll
        for (int s = 0; s < 4; s++) {
            int idx = tid + s * 256;
            int n = idx >> 3, gq = idx & 7;
            size_t src = (size_t)(half * 128 + n) * 256 + k0 + gq * 8;
            *(uint4*)(sm + EOFF_B + n * 160 + gq * 16) = *(const uint4*)(b_g + src);
        }
        __syncthreads();

        // ---- compute 4 k16 steps, 2 passes ------------------------------
        #pragma unroll
        for (int ks = 0; ks < 4; ks++) {
            const uint32_t koff = (uint32_t)(ks * 16 + lkh) * 2;
            uint32_t ah[2][4], al[2][4], b[2][4];
            #pragma unroll
            for (int mi = 0; mi < 2; mi++) {
                uint32_t addr = sb + EOFF_AHI + (uint32_t)(wm*32 + mi*16 + lrow) * 160 + koff;
                LDSM4(ah[mi], addr);
                LDSM4(al[mi], addr + (EOFF_ALO - EOFF_AHI));
            }
            #pragma unroll
            for (int gj = 0; gj < 2; gj++) {
                uint32_t addr = sb + EOFF_B + (uint32_t)(wn*32 + gj*16 + lrow) * 160 + koff;
                LDSM4(b[gj], addr);
            }
            #pragma unroll
            for (int mi = 0; mi < 2; mi++)
                #pragma unroll
                for (int ni = 0; ni < 4; ni++) {
                    int gj = ni >> 1, up = ni & 1;
                    uint32_t b0 = b[gj][up], b1 = b[gj][up + 2];
                    MMA16816H(acc[mi][ni], ah[mi], b0, b1);
                    MMA16816H(acc[mi][ni], al[mi], b0, b1);
                }
        }
    }
}

// ===========================================================================
// Preprocessing kernels
// ===========================================================================
__global__ void zero_deg_kernel() {
    int i = blockIdx.x * blockDim.x + threadIdx.x;
    if (i < NN) g_deg[i] = 0;
}

__global__ void convert_hist_kernel(const void* ei) {
    __shared__ int s_is64;
    if (threadIdx.x < 32) {
        const long long* p = (const long long*)ei;
        int bad = 0;
        for (int i = threadIdx.x; i < 512; i += 32) {
            long long v = p[i];
            if (v < 0 || v >= NN) bad = 1;
        }
        bad = __any_sync(0xffffffffu, bad);
        if (threadIdx.x == 0) s_is64 = bad ? 0 : 1;
    }
    __syncthreads();
    int i = blockIdx.x * blockDim.x + threadIdx.x;
    if (i < EE) {
        int r, c;
        if (s_is64) {
            const long long* p = (const long long*)ei;
            r = (int)p[i]; c = (int)p[EE + i];
        } else {
            const int* p = (const int*)ei;
            r = p[i]; c = p[EE + i];
        }
        g_row[i] = r; g_col[i] = c;
        atomicAdd(&g_deg[c], 1);
    }
}

#define SCAN_BLOCKS 63
__global__ void scanA_kernel() {
    __shared__ int s[256];
    int b = blockIdx.x, t = threadIdx.x;
    int i = b * 256 + t;
    int v = (i < NN) ? g_deg[i] : 0;
    s[t] = v;
    __syncthreads();
    #pragma unroll
    for (int off = 1; off < 256; off <<= 1) {
        int u = (t >= off) ? s[t - off] : 0;
        __syncthreads();
        s[t] += u;
        __syncthreads();
    }
    if (i < NN) g_off[i] = s[t] - v;
    if (t == 255) g_bsum[b] = s[255];
}

__global__ void scanC_kernel() {
    __shared__ int s[64];
    int b = blockIdx.x, t = threadIdx.x;
    if (t < 64) s[t] = (t < SCAN_BLOCKS) ? g_bsum[t] : 0;
    __syncthreads();
    #pragma unroll
    for (int off = 1; off < 64; off <<= 1) {
        int u = (t >= off && t < 64) ? s[t - off] : 0;
        __syncthreads();
        if (t < 64) s[t] += u;
        __syncthreads();
    }
    int pref = (b == 0) ? 0 : s[b - 1];
    int i = b * 256 + t;
    if (i < NN) {
        int o = g_off[i] + pref;
        g_off[i] = o;
        g_cursor[i] = o;
    }
    if (b == 0 && t == 0) g_off[NN] = s[SCAN_BLOCKS - 1];
}

__global__ void fill_kernel() {
    int i = blockIdx.x * blockDim.x + threadIdx.x;
    if (i < EE) {
        int c = g_col[i];
        int p = atomicAdd(&g_cursor[c], 1);
        g_eid[p] = i;
    }
}

// Transpose weights. mats 0..2 -> bf16 hi/lo (qkv); mat 3 -> single fp16 (We).
__global__ void wtrans_kernel(const float* __restrict__ Wq, const float* __restrict__ Wk,
                              const float* __restrict__ Wv, const float* __restrict__ We) {
    int mat = blockIdx.y;
    const float* W = (mat == 0) ? Wq : (mat == 1) ? Wk : (mat == 2) ? Wv : We;
    int idx = blockIdx.x * 256 + threadIdx.x;
    int n = idx & 255;
    int k = idx >> 8;
    float v = W[(size_t)k * 256 + n];
    if (mat < 3) {
        __nv_bfloat16 h = __float2bfloat16(v);
        __nv_bfloat16 l = __float2bfloat16(v - __bfloat162float(h));
        g_bt_hi[(size_t)mat * 65536 + (size_t)n * 256 + k] = h;
        g_bt_lo[(size_t)mat * 65536 + (size_t)n * 256 + k] = l;
    } else {
        g_we_h[(size_t)n * 256 + k] = __float2half(v);
    }
}

// ===========================================================================
// q/k/v tensor-core GEMM (bf16 3-pass). grid (250, 2, 3), 256 threads.
// ===========================================================================
__global__ __launch_bounds__(256, 2) void qkv_mma_kernel(const float* __restrict__ x) {
    extern __shared__ char sm[];
    uint32_t sb = smem_u32(sm);
    int tid = threadIdx.x;
    int m0   = blockIdx.x * 64;
    int half = blockIdx.y;
    int mat  = blockIdx.z;

    float acc[2][4][4] = {};
    gemm_tile_bf16(sm, sb, x + (size_t)m0 * 256,
                   g_bt_hi + (size_t)mat * 65536, g_bt_lo + (size_t)mat * 65536,
                   half, tid, acc);

    float* outp = (mat == 0) ? g_q : (mat == 1) ? g_k : g_v;
    int wid = tid >> 5, lane = tid & 31;
    int wm = wid & 1, wn = wid >> 1;
    int g = lane >> 2, quad = lane & 3;
    int cbase = half * 128 + wn * 32 + quad * 2;

    #pragma unroll
    for (int mi = 0; mi < 2; mi++)
        #pragma unroll
        for (int hh = 0; hh < 2; hh++) {
            int row = m0 + wm*32 + mi*16 + hh*8 + g;
            #pragma unroll
            for (int ni = 0; ni < 4; ni++)
                *(float2*)(outp + (size_t)row * 256 + cbase + ni*8) =
                    make_float2(acc[mi][ni][hh*2], acc[mi][ni][hh*2+1]);
        }
}

// ===========================================================================
// Edge GEMM (fp16 2-pass) + fused attention epilogue. grid 8000:
// tile = bid>>1, half = bid&1 (co-resident halves -> A tile L2 reuse).
// ===========================================================================
__global__ __launch_bounds__(256, 2) void edge_mma_kernel(
    const float* __restrict__ edge_attr,
    const float* __restrict__ coords,
    const float* __restrict__ We,
    float* __restrict__ out)
{
    extern __shared__ char sm[];
    uint32_t sb = smem_u32(sm);
    int tid = threadIdx.x;
    int e0   = (blockIdx.x >> 1) * 64;
    int half = blockIdx.x & 1;

    if (tid < 64) {
        int e = e0 + tid;
        int r = g_row[e], c = g_col[e];
        ((int*)(sm + EOFF_RN))[tid] = r;
        ((int*)(sm + EOFF_CN))[tid] = c;
        float dx = coords[r*3+0] - coords[c*3+0];
        float dy = coords[r*3+1] - coords[c*3+1];
        float dz = coords[r*3+2] - coords[c*3+2];
        ((float*)(sm + EOFF_DIST))[tid] = 0.1f * sqrtf(dx*dx + dy*dy + dz*dz);
    }

    float acc[2][4][4] = {};
    gemm_tile_f16(sm, sb, edge_attr + (size_t)e0 * 256,
                  g_we_h, half, tid, acc);

    int wid = tid >> 5, lane = tid & 31;
    int wm = wid & 1, wn = wid >> 1;
    int g = lane >> 2, quad = lane & 3;
    int head  = half * 4 + wn;
    int cbase = half * 128 + wn * 32 + quad * 2;

    float wl[4][2];
    #pragma unroll
    for (int ni = 0; ni < 4; ni++) {
        float2 w = *(const float2*)(We + (size_t)256 * 256 + cbase + ni*8);
        wl[ni][0] = w.x; wl[ni][1] = w.y;
    }

    const float inv_sqrt_d = 0.17677669529663687f;  // 1/sqrt(32)
    float* eout = out + EOUT_OFF;

    #pragma unroll
    for (int mi = 0; mi < 2; mi++)
        #pragma unroll
        for (int hh = 0; hh < 2; hh++) {
            int m = wm*32 + mi*16 + hh*8 + g;
            int e = e0 + m;
            int rn = ((int*)(sm + EOFF_RN))[m];
            int cn = ((int*)(sm + EOFF_CN))[m];
            float dist = ((float*)(sm + EOFF_DIST))[m];
            float sum = 0.0f;
            #pragma unroll
            for (int ni = 0; ni < 4; ni++) {
                int c = cbase + ni*8;
                float2 q2 = *(const float2*)(g_q + (size_t)cn * 256 + c);
                float2 k2 = *(const float2*)(g_k + (size_t)rn * 256 + c);
                float ea0 = fmaf(dist, wl[ni][0], acc[mi][ni][hh*2+0]);
                float ea1 = fmaf(dist, wl[ni][1], acc[mi][ni][hh*2+1]);
                float t0 = fminf(5.0f, fmaxf(-5.0f, k2.x * q2.x * inv_sqrt_d));
                float t1 = fminf(5.0f, fmaxf(-5.0f, k2.y * q2.y * inv_sqrt_d));
                float a0 = t0 * ea0, a1 = t1 * ea1;
                *(float2*)(eout + (size_t)e * 256 + c) = make_float2(a0, a1);
                sum += a0 + a1;
            }
            sum += __shfl_xor_sync(0xffffffffu, sum, 1);
            sum += __shfl_xor_sync(0xffffffffu, sum, 2);
            if (quad == 0)
                g_ax[(size_t)e * HH + head] =
                    expf(fminf(5.0f, fmaxf(-5.0f, sum)));
        }
}

// ===========================================================================
// Gather + finalize: one block per destination node, no atomics.
// ===========================================================================
__global__ __launch_bounds__(256) void gather_kernel(
    const float* __restrict__ coords,
    float* __restrict__ out)
{
    __shared__ int   sr[256];
    __shared__ float sax[256 * HH];

    int n   = blockIdx.x;
    int tid = threadIdx.x;
    int h   = tid >> 5;

    int off = g_off[n];
    int end = g_off[n + 1];

    float acc  = 0.0f;
    float zacc = 0.0f;

    for (int base = off; base < end; base += 256) {
        int cnt = min(256, end - base);
        __syncthreads();
        for (int t = tid; t < cnt; t += 256)
            sr[t] = g_row[g_eid[base + t]];
        for (int t = tid; t < cnt * HH; t += 256) {
            int e = g_eid[base + (t >> 3)];
            sax[t] = g_ax[(size_t)e * HH + (t & 7)];
        }
        __syncthreads();
        #pragma unroll 8
        for (int j = 0; j < cnt; j++)
            acc = fmaf(g_v[(size_t)sr[j] * HD + tid], sax[j * HH + h], acc);
        if ((tid & 31) == 0)
            for (int j = 0; j < cnt; j++) zacc += sax[j * HH + h];
    }

    float z = __shfl_sync(0xffffffffu, zacc, 0);
    out[(size_t)n * HD + tid] = acc / (z + 1e-6f);

    if (tid < 3) out[COORD_OFF + n*3 + tid] = coords[n*3 + tid];
}

// ===========================================================================
extern "C" void kernel_launch(void* const* d_in, const int* in_sizes, int n_in,
                              void* d_out, int out_size)
{
    const float* x         = (const float*)d_in[0];
    const float* edge_attr = (const float*)d_in[1];
    const void*  ei        = d_in[2];
    const float* coords    = (const float*)d_in[3];
    const float* Wq        = (const float*)d_in[4];
    const float* Wk        = (const float*)d_in[5];
    const float* Wv        = (const float*)d_in[6];
    const float* We        = (const float*)d_in[7];
    float* out = (float*)d_out;

    static cudaStream_t s2 = nullptr;
    static cudaEvent_t  e_fork = nullptr, e_conv = nullptr, e_fill = nullptr;
    if (!s2) {
        cudaFuncSetAttribute(qkv_mma_kernel,
                             cudaFuncAttributeMaxDynamicSharedMemorySize, SMEM_QKV);
        cudaFuncSetAttribute(edge_mma_kernel,
                             cudaFuncAttributeMaxDynamicSharedMemorySize, SMEM_EDGE);
        cudaStreamCreateWithFlags(&s2, cudaStreamNonBlocking);
        cudaEventCreateWithFlags(&e_fork, cudaEventDisableTiming);
        cudaEventCreateWithFlags(&e_conv, cudaEventDisableTiming);
        cudaEventCreateWithFlags(&e_fill, cudaEventDisableTiming);
    }

    // ---- fork: CSR preprocessing chain on s2 ----------------------------
    cudaEventRecord(e_fork, 0);
    cudaStreamWaitEvent(s2, e_fork, 0);

    zero_deg_kernel<<<(NN + 255) / 256, 256, 0, s2>>>();
    convert_hist_kernel<<<(EE + 255) / 256, 256, 0, s2>>>(ei);
    cudaEventRecord(e_conv, s2);
    scanA_kernel<<<SCAN_BLOCKS, 256, 0, s2>>>();
    scanC_kernel<<<SCAN_BLOCKS, 256, 0, s2>>>();
    fill_kernel<<<(EE + 255) / 256, 256, 0, s2>>>();
    cudaEventRecord(e_fill, s2);

    // ---- main stream: weights + qkv (independent of edge_index) ---------
    dim3 gtr(256, 4);
    wtrans_kernel<<<gtr, 256>>>(Wq, Wk, Wv, We);

    dim3 gqkv(250, 2, 3);
    qkv_mma_kernel<<<gqkv, 256, SMEM_QKV>>>(x);

    // edge needs g_row/g_col (convert) + qkv + wtrans
    cudaStreamWaitEvent(0, e_conv, 0);
    edge_mma_kernel<<<8000, 256, SMEM_EDGE>>>(edge_attr, coords, We, out);

    // gather needs CSR (fill) + g_ax (edge)
    cudaStreamWaitEvent(0, e_fill, 0);
    gather_kernel<<<NN, 256>>>(coords, out);
}